// round 13
// baseline (speedup 1.0000x reference)
#include <cuda_runtime.h>
#include <cstdint>

// ----------------------------------------------------------------------------
// SimpleVQVAE forward, all GEMMs on tensor cores via mma.sync.m16n8k8.tf32
// with 3xTF32 error compensation. Smem tiles stored PRE-SPLIT as (hi,lo) tf32
// pairs so the MMA loop has zero CVT work. BK=16, block 128x128, 8 warps.
// Activations in [B, T, C] layout (channel-contiguous).
// ----------------------------------------------------------------------------

static __device__ float g_bufA[16UL * 2048 * 512];     // 64 MB
static __device__ float g_bufB[16UL * 2048 * 512];     // 64 MB
static __device__ float g_scores[32768UL * 1024];      // 128 MB
static __device__ float g_wT[3UL * 512 * 1024];        // wT[k][ci][co_pad]
static __device__ float g_cnorm[1024];
static __device__ int   g_idx[32768];

__device__ __forceinline__ uint32_t f2tf32(float f) {
    uint32_t r;
    asm("cvt.rna.tf32.f32 %0, %1;" : "=r"(r) : "f"(f));
    return r;
}
__device__ __forceinline__ void split_tf32(float v, uint32_t& hi, uint32_t& lo) {
    hi = f2tf32(v);
    lo = f2tf32(v - __uint_as_float(hi));
}
__device__ __forceinline__ void mma_tf32(float* c, const uint32_t* a, const uint32_t* b) {
    asm volatile(
        "mma.sync.aligned.m16n8k8.row.col.f32.tf32.tf32.f32 "
        "{%0,%1,%2,%3}, {%4,%5,%6,%7}, {%8,%9}, {%0,%1,%2,%3};"
        : "+f"(c[0]), "+f"(c[1]), "+f"(c[2]), "+f"(c[3])
        : "r"(a[0]), "r"(a[1]), "r"(a[2]), "r"(a[3]), "r"(b[0]), "r"(b[1]));
}

// ---- weight transpose: w[CO][CI][TAPS] -> wT[TAPS][CI][CO_pad], zero pad ----
__global__ void transpose_w(const float* __restrict__ w, float* __restrict__ wT,
                            int CO, int CI, int TAPS, int CO_pad) {
    long total = (long)TAPS * CI * CO_pad;
    for (long i = (long)blockIdx.x * blockDim.x + threadIdx.x; i < total;
         i += (long)gridDim.x * blockDim.x) {
        int  co = (int)(i % CO_pad);
        long r  = i / CO_pad;
        int  ci = (int)(r % CI);
        int  k  = (int)(r / CI);
        wT[i] = (co < CO) ? w[((long)co * CI + ci) * TAPS + k] : 0.f;
    }
}

// ===================== tensor-core conv1d-as-GEMM (3xTF32) ==================
// Block: 128(M=time) x 128(N=co), BK=16, 8 warps (4M x 2N), warp tile 32x64.
// Smem tiles hold pre-split tf32 (hi,lo).
#define APAD 4   // A row stride 20 words -> conflict-free frag reads
#define BPAD 8   // B row stride 136 words -> conflict-free frag reads
template <int TAPS, bool RELU, bool BIAS>
__global__ void __launch_bounds__(256)
conv_mma(const float* __restrict__ x, const float* __restrict__ wT,
         const float* __restrict__ addvec, float* __restrict__ y,
         int T, int CI, int CO, int CO_pad, float alpha) {
    __shared__ uint32_t AsH[128][16 + APAD];
    __shared__ uint32_t AsL[128][16 + APAD];
    __shared__ uint32_t BsH[16][128 + BPAD];
    __shared__ uint32_t BsL[16][128 + BPAD];

    const int t0  = blockIdx.x * 128;
    const int co0 = blockIdx.y * 128;
    const float* xb = x + (size_t)blockIdx.z * T * CI;
    float*       yb = y + (size_t)blockIdx.z * T * CO;

    const int tid   = threadIdx.x;
    const int wid   = tid >> 5, lane = tid & 31;
    const int warpM = wid & 3, warpN = wid >> 2;           // 4 x 2 warps
    const int grp   = lane >> 2, quad = lane & 3;          // fragment coords

    // loader coords
    const int aRow = tid >> 1, aHalf = tid & 1;            // A: 128 rows x 2 halves(8 f)
    const int bRow = tid >> 4, bColq = tid & 15;           // B: 16 rows x 16 chunks(8 f)

    float c[2][8][4];
#pragma unroll
    for (int mt = 0; mt < 2; mt++)
#pragma unroll
        for (int nt = 0; nt < 8; nt++)
#pragma unroll
            for (int r = 0; r < 4; r++) c[mt][nt][r] = 0.f;

    for (int k = 0; k < TAPS; k++) {                       // not unrolled (compile size)
        const int tshift = (TAPS == 1) ? 0 : (k - 1);
        for (int ci0 = 0; ci0 < CI; ci0 += 16) {
            // ---- A tile: 128 rows x 16 ci, split into (hi,lo) ----
            {
                int tg = t0 + aRow + tshift;
                float4 a0 = make_float4(0.f, 0.f, 0.f, 0.f);
                float4 a1 = make_float4(0.f, 0.f, 0.f, 0.f);
                if (tg >= 0 && tg < T) {
                    const float* p = xb + (size_t)tg * CI + ci0 + aHalf * 8;
                    a0 = *reinterpret_cast<const float4*>(p);
                    a1 = *reinterpret_cast<const float4*>(p + 4);
                }
                int cbase = aHalf * 8;
                float av[8] = {a0.x, a0.y, a0.z, a0.w, a1.x, a1.y, a1.z, a1.w};
#pragma unroll
                for (int e = 0; e < 8; e++)
                    split_tf32(av[e], AsH[aRow][cbase + e], AsL[aRow][cbase + e]);
            }
            // ---- B tile: 16 k-rows x 128 co, split into (hi,lo) ----
            {
                const float* p = wT + ((size_t)k * CI + ci0 + bRow) * CO_pad + co0 + bColq * 8;
                float4 b0 = *reinterpret_cast<const float4*>(p);
                float4 b1 = *reinterpret_cast<const float4*>(p + 4);
                int nbase = bColq * 8;
                float bv[8] = {b0.x, b0.y, b0.z, b0.w, b1.x, b1.y, b1.z, b1.w};
#pragma unroll
                for (int e = 0; e < 8; e++)
                    split_tf32(bv[e], BsH[bRow][nbase + e], BsL[bRow][nbase + e]);
            }
            __syncthreads();

#pragma unroll
            for (int kk = 0; kk < 16; kk += 8) {
                uint32_t ah[2][4], al[2][4];
#pragma unroll
                for (int mt = 0; mt < 2; mt++) {
                    int m = warpM * 32 + mt * 16 + grp;
                    ah[mt][0] = AsH[m][kk + quad];      al[mt][0] = AsL[m][kk + quad];
                    ah[mt][1] = AsH[m + 8][kk + quad];  al[mt][1] = AsL[m + 8][kk + quad];
                    ah[mt][2] = AsH[m][kk + quad + 4];  al[mt][2] = AsL[m][kk + quad + 4];
                    ah[mt][3] = AsH[m + 8][kk + quad + 4]; al[mt][3] = AsL[m + 8][kk + quad + 4];
                }
#pragma unroll
                for (int nt = 0; nt < 8; nt++) {
                    int n = warpN * 64 + nt * 8 + grp;
                    uint32_t bh[2], bl[2];
                    bh[0] = BsH[kk + quad][n];     bl[0] = BsL[kk + quad][n];
                    bh[1] = BsH[kk + quad + 4][n]; bl[1] = BsL[kk + quad + 4][n];
#pragma unroll
                    for (int mt = 0; mt < 2; mt++) {
                        mma_tf32(c[mt][nt], ah[mt], bh);
                        mma_tf32(c[mt][nt], ah[mt], bl);
                        mma_tf32(c[mt][nt], al[mt], bh);
                    }
                }
            }
            __syncthreads();
        }
    }

    // ---- epilogue ----
#pragma unroll
    for (int mt = 0; mt < 2; mt++) {
        int r0 = t0 + warpM * 32 + mt * 16 + grp;
#pragma unroll
        for (int nt = 0; nt < 8; nt++) {
            int n = co0 + warpN * 64 + nt * 8 + 2 * quad;
#pragma unroll
            for (int half = 0; half < 2; half++) {
                int row = r0 + half * 8;
                float* yr = yb + (size_t)row * CO;
#pragma unroll
                for (int e = 0; e < 2; e++) {
                    int co = n + e;
                    if (co < CO) {
                        float v = alpha * c[mt][nt][half * 2 + e];
                        if (BIAS) v += addvec[co];
                        if (RELU) v = fmaxf(v, 0.f);
                        yr[co] = v;
                    }
                }
            }
        }
    }
}

// ======================= VQ tail kernels (fp32) =============================
__global__ void cnorm_kernel(const float* __restrict__ cb, float* __restrict__ cn) {
    int row  = blockIdx.x * (blockDim.x >> 5) + (threadIdx.x >> 5);
    int lane = threadIdx.x & 31;
    if (row >= 1024) return;
    const float* c = cb + (size_t)row * 512;
    float s = 0.f;
    for (int i = lane; i < 512; i += 32) { float v = c[i]; s += v * v; }
#pragma unroll
    for (int o = 16; o; o >>= 1) s += __shfl_xor_sync(0xffffffffu, s, o);
    if (lane == 0) cn[row] = s;
}

__global__ void argmin_kernel(const float* __restrict__ s, const float* __restrict__ cn,
                              int* __restrict__ idx) {
    int row  = blockIdx.x * (blockDim.x >> 5) + (threadIdx.x >> 5);
    int lane = threadIdx.x & 31;
    if (row >= 32768) return;
    const float* r = s + (size_t)row * 1024;
    float best = 3.402823466e38f;
    int   bi   = 0x7fffffff;
#pragma unroll 4
    for (int i = 0; i < 32; i++) {
        int   cidx = lane + (i << 5);
        float v = r[cidx] + cn[cidx];
        if (v < best || (v == best && cidx < bi)) { best = v; bi = cidx; }
    }
#pragma unroll
    for (int o = 16; o; o >>= 1) {
        float ov = __shfl_xor_sync(0xffffffffu, best, o);
        int   oi = __shfl_xor_sync(0xffffffffu, bi, o);
        if (ov < best || (ov == best && oi < bi)) { best = ov; bi = oi; }
    }
    if (lane == 0) idx[row] = bi;
}

__global__ void gather_kernel(const float* __restrict__ cb, const int* __restrict__ idx,
                              float* __restrict__ q) {
    long gid = (long)blockIdx.x * blockDim.x + threadIdx.x;
    if (gid >= 32768L * 128) return;
    int n  = (int)(gid >> 7);
    int d4 = (int)(gid & 127);
    reinterpret_cast<float4*>(q)[(long)n * 128 + d4] =
        reinterpret_cast<const float4*>(cb)[(long)idx[n] * 128 + d4];
}

__global__ void idx_to_float(const int* __restrict__ idx, float* __restrict__ out, int n) {
    int i = blockIdx.x * blockDim.x + threadIdx.x;
    if (i < n) out[i] = (float)idx[i];
}

// ----------------------------------------------------------------------------
extern "C" void kernel_launch(void* const* d_in, const int* in_sizes, int n_in,
                              void* d_out, int out_size) {
    const float* mels   = (const float*)d_in[0];
    const float* enc_w1 = (const float*)d_in[1];
    const float* enc_b1 = (const float*)d_in[2];
    const float* enc_w2 = (const float*)d_in[3];
    const float* enc_b2 = (const float*)d_in[4];
    const float* cb     = (const float*)d_in[5];
    const float* dec_w1 = (const float*)d_in[6];
    const float* dec_b1 = (const float*)d_in[7];
    const float* dec_w2 = (const float*)d_in[8];
    const float* dec_b2 = (const float*)d_in[9];

    float *bufA, *bufB, *scores, *wT, *cn;
    int*   idxp;
    cudaGetSymbolAddress((void**)&bufA,   g_bufA);
    cudaGetSymbolAddress((void**)&bufB,   g_bufB);
    cudaGetSymbolAddress((void**)&scores, g_scores);
    cudaGetSymbolAddress((void**)&wT,     g_wT);
    cudaGetSymbolAddress((void**)&cn,     g_cnorm);
    cudaGetSymbolAddress((void**)&idxp,   g_idx);

    const int B = 16, T = 2048, IN = 80, H = 512, D = 512, K = 1024;
    const int BT = B * T;
    const int RECON = B * T * IN;

    // ---- encoder conv1: mels[B,T,80] -> bufA, relu ----
    transpose_w<<<256, 256>>>(enc_w1, wT, H, IN, 3, H);
    conv_mma<3, true, true><<<dim3(T / 128, H / 128, B), 256>>>(
        mels, wT, enc_b1, bufA, T, IN, H, H, 1.f);

    // ---- encoder conv2: bufA -> bufB (z) ----
    transpose_w<<<256, 256>>>(enc_w2, wT, D, H, 3, D);
    conv_mma<3, false, true><<<dim3(T / 128, D / 128, B), 256>>>(
        bufA, wT, enc_b2, bufB, T, H, D, D, 1.f);

    // ---- VQ: scores[n,k] = -2 z_n . c_k ; argmin adds ||c_k||^2 ----
    cnorm_kernel<<<1024 / 8, 256>>>(cb, cn);
    transpose_w<<<256, 256>>>(cb, wT, K, D, 1, K);
    conv_mma<1, false, false><<<dim3(BT / 128, K / 128, 1), 256>>>(
        bufB, wT, nullptr, scores, BT, D, K, K, -2.f);
    argmin_kernel<<<BT / 8, 256>>>(scores, cn, idxp);
    gather_kernel<<<(BT * 128 + 255) / 256, 256>>>(cb, idxp, bufA);

    // ---- decoder conv1: bufA -> bufB, relu ----
    transpose_w<<<256, 256>>>(dec_w1, wT, H, D, 3, H);
    conv_mma<3, true, true><<<dim3(T / 128, H / 128, B), 256>>>(
        bufA, wT, dec_b1, bufB, T, D, H, H, 1.f);

    // ---- decoder conv2: bufB -> recon [B,T,80] (into d_out) ----
    transpose_w<<<256, 256>>>(dec_w2, wT, IN, H, 3, 128);
    float* recon = (float*)d_out;
    conv_mma<3, false, true><<<dim3(T / 128, 1, B), 256>>>(
        bufB, wT, dec_b2, recon, T, H, IN, 128, 1.f);

    if (out_size >= RECON + BT) {
        idx_to_float<<<(BT + 255) / 256, 256>>>(idxp, recon + RECON, BT);
    }
}

// round 14
// speedup vs baseline: 1.1765x; 1.1765x over previous
#include <cuda_runtime.h>
#include <cstdint>

// ----------------------------------------------------------------------------
// SimpleVQVAE forward, all GEMMs on tensor cores via mma.sync.m16n8k8.tf32
// with 3xTF32 error compensation. Smem tiles stored PRE-SPLIT as (hi,lo) tf32
// pairs so the MMA loop has zero CVT work. BK=16, block 128x128, 8 warps.
// __launch_bounds__(256,2) pins 2 CTAs/SM (<=128 regs) — R13 regressed only
// because 140 regs crossed the 2-CTA regfile boundary.
// ----------------------------------------------------------------------------

static __device__ float g_bufA[16UL * 2048 * 512];     // 64 MB
static __device__ float g_bufB[16UL * 2048 * 512];     // 64 MB
static __device__ float g_scores[32768UL * 1024];      // 128 MB
static __device__ float g_wT[3UL * 512 * 1024];        // wT[k][ci][co_pad]
static __device__ float g_cnorm[1024];
static __device__ int   g_idx[32768];

__device__ __forceinline__ uint32_t f2tf32(float f) {
    uint32_t r;
    asm("cvt.rna.tf32.f32 %0, %1;" : "=r"(r) : "f"(f));
    return r;
}
__device__ __forceinline__ void split_tf32(float v, uint32_t& hi, uint32_t& lo) {
    hi = f2tf32(v);
    lo = f2tf32(v - __uint_as_float(hi));
}
__device__ __forceinline__ void mma_tf32(float* c, const uint32_t* a, const uint32_t* b) {
    asm volatile(
        "mma.sync.aligned.m16n8k8.row.col.f32.tf32.tf32.f32 "
        "{%0,%1,%2,%3}, {%4,%5,%6,%7}, {%8,%9}, {%0,%1,%2,%3};"
        : "+f"(c[0]), "+f"(c[1]), "+f"(c[2]), "+f"(c[3])
        : "r"(a[0]), "r"(a[1]), "r"(a[2]), "r"(a[3]), "r"(b[0]), "r"(b[1]));
}

// ---- weight transpose: w[CO][CI][TAPS] -> wT[TAPS][CI][CO_pad], zero pad ----
__global__ void transpose_w(const float* __restrict__ w, float* __restrict__ wT,
                            int CO, int CI, int TAPS, int CO_pad) {
    long total = (long)TAPS * CI * CO_pad;
    for (long i = (long)blockIdx.x * blockDim.x + threadIdx.x; i < total;
         i += (long)gridDim.x * blockDim.x) {
        int  co = (int)(i % CO_pad);
        long r  = i / CO_pad;
        int  ci = (int)(r % CI);
        int  k  = (int)(r / CI);
        wT[i] = (co < CO) ? w[((long)co * CI + ci) * TAPS + k] : 0.f;
    }
}

// ===================== tensor-core conv1d-as-GEMM (3xTF32) ==================
// Block: 128(M=time) x 128(N=co), BK=16, 8 warps (4M x 2N), warp tile 32x64.
// Smem tiles hold pre-split tf32 (hi,lo).
#define APAD 4   // A row stride 20 words -> conflict-free frag reads
#define BPAD 8   // B row stride 136 words -> conflict-free frag reads
template <int TAPS, bool RELU, bool BIAS>
__global__ void __launch_bounds__(256, 2)
conv_mma(const float* __restrict__ x, const float* __restrict__ wT,
         const float* __restrict__ addvec, float* __restrict__ y,
         int T, int CI, int CO, int CO_pad, float alpha) {
    __shared__ uint32_t AsH[128][16 + APAD];
    __shared__ uint32_t AsL[128][16 + APAD];
    __shared__ uint32_t BsH[16][128 + BPAD];
    __shared__ uint32_t BsL[16][128 + BPAD];

    const int t0  = blockIdx.x * 128;
    const int co0 = blockIdx.y * 128;
    const float* xb = x + (size_t)blockIdx.z * T * CI;
    float*       yb = y + (size_t)blockIdx.z * T * CO;

    const int tid   = threadIdx.x;
    const int wid   = tid >> 5, lane = tid & 31;
    const int warpM = wid & 3, warpN = wid >> 2;           // 4 x 2 warps
    const int grp   = lane >> 2, quad = lane & 3;          // fragment coords

    // loader coords
    const int aRow = tid >> 1, aHalf = tid & 1;            // A: 128 rows x 2 halves(8 f)
    const int bRow = tid >> 4, bColq = tid & 15;           // B: 16 rows x 16 chunks(8 f)

    float c[2][8][4];
#pragma unroll
    for (int mt = 0; mt < 2; mt++)
#pragma unroll
        for (int nt = 0; nt < 8; nt++)
#pragma unroll
            for (int r = 0; r < 4; r++) c[mt][nt][r] = 0.f;

    for (int k = 0; k < TAPS; k++) {                       // not unrolled (compile size)
        const int tshift = (TAPS == 1) ? 0 : (k - 1);
        for (int ci0 = 0; ci0 < CI; ci0 += 16) {
            // ---- A tile: 128 rows x 16 ci, split into (hi,lo) ----
            {
                int tg = t0 + aRow + tshift;
                float4 a0 = make_float4(0.f, 0.f, 0.f, 0.f);
                float4 a1 = make_float4(0.f, 0.f, 0.f, 0.f);
                if (tg >= 0 && tg < T) {
                    const float* p = xb + (size_t)tg * CI + ci0 + aHalf * 8;
                    a0 = *reinterpret_cast<const float4*>(p);
                    a1 = *reinterpret_cast<const float4*>(p + 4);
                }
                int cbase = aHalf * 8;
                float av[8] = {a0.x, a0.y, a0.z, a0.w, a1.x, a1.y, a1.z, a1.w};
#pragma unroll
                for (int e = 0; e < 8; e++)
                    split_tf32(av[e], AsH[aRow][cbase + e], AsL[aRow][cbase + e]);
            }
            // ---- B tile: 16 k-rows x 128 co, split into (hi,lo) ----
            {
                const float* p = wT + ((size_t)k * CI + ci0 + bRow) * CO_pad + co0 + bColq * 8;
                float4 b0 = *reinterpret_cast<const float4*>(p);
                float4 b1 = *reinterpret_cast<const float4*>(p + 4);
                int nbase = bColq * 8;
                float bv[8] = {b0.x, b0.y, b0.z, b0.w, b1.x, b1.y, b1.z, b1.w};
#pragma unroll
                for (int e = 0; e < 8; e++)
                    split_tf32(bv[e], BsH[bRow][nbase + e], BsL[bRow][nbase + e]);
            }
            __syncthreads();

#pragma unroll
            for (int kk = 0; kk < 16; kk += 8) {
                uint32_t ah[2][4], al[2][4];
#pragma unroll
                for (int mt = 0; mt < 2; mt++) {
                    int m = warpM * 32 + mt * 16 + grp;
                    ah[mt][0] = AsH[m][kk + quad];      al[mt][0] = AsL[m][kk + quad];
                    ah[mt][1] = AsH[m + 8][kk + quad];  al[mt][1] = AsL[m + 8][kk + quad];
                    ah[mt][2] = AsH[m][kk + quad + 4];  al[mt][2] = AsL[m][kk + quad + 4];
                    ah[mt][3] = AsH[m + 8][kk + quad + 4]; al[mt][3] = AsL[m + 8][kk + quad + 4];
                }
#pragma unroll
                for (int nt = 0; nt < 8; nt++) {
                    int n = warpN * 64 + nt * 8 + grp;
                    uint32_t bh[2], bl[2];
                    bh[0] = BsH[kk + quad][n];     bl[0] = BsL[kk + quad][n];
                    bh[1] = BsH[kk + quad + 4][n]; bl[1] = BsL[kk + quad + 4][n];
#pragma unroll
                    for (int mt = 0; mt < 2; mt++) {
                        mma_tf32(c[mt][nt], ah[mt], bh);
                        mma_tf32(c[mt][nt], ah[mt], bl);
                        mma_tf32(c[mt][nt], al[mt], bh);
                    }
                }
            }
            __syncthreads();
        }
    }

    // ---- epilogue ----
#pragma unroll
    for (int mt = 0; mt < 2; mt++) {
        int r0 = t0 + warpM * 32 + mt * 16 + grp;
#pragma unroll
        for (int nt = 0; nt < 8; nt++) {
            int n = co0 + warpN * 64 + nt * 8 + 2 * quad;
#pragma unroll
            for (int half = 0; half < 2; half++) {
                int row = r0 + half * 8;
                float* yr = yb + (size_t)row * CO;
#pragma unroll
                for (int e = 0; e < 2; e++) {
                    int co = n + e;
                    if (co < CO) {
                        float v = alpha * c[mt][nt][half * 2 + e];
                        if (BIAS) v += addvec[co];
                        if (RELU) v = fmaxf(v, 0.f);
                        yr[co] = v;
                    }
                }
            }
        }
    }
}

// ======================= VQ tail kernels (fp32) =============================
__global__ void cnorm_kernel(const float* __restrict__ cb, float* __restrict__ cn) {
    int row  = blockIdx.x * (blockDim.x >> 5) + (threadIdx.x >> 5);
    int lane = threadIdx.x & 31;
    if (row >= 1024) return;
    const float* c = cb + (size_t)row * 512;
    float s = 0.f;
    for (int i = lane; i < 512; i += 32) { float v = c[i]; s += v * v; }
#pragma unroll
    for (int o = 16; o; o >>= 1) s += __shfl_xor_sync(0xffffffffu, s, o);
    if (lane == 0) cn[row] = s;
}

__global__ void argmin_kernel(const float* __restrict__ s, const float* __restrict__ cn,
                              int* __restrict__ idx) {
    int row  = blockIdx.x * (blockDim.x >> 5) + (threadIdx.x >> 5);
    int lane = threadIdx.x & 31;
    if (row >= 32768) return;
    const float* r = s + (size_t)row * 1024;
    float best = 3.402823466e38f;
    int   bi   = 0x7fffffff;
#pragma unroll 4
    for (int i = 0; i < 32; i++) {
        int   cidx = lane + (i << 5);
        float v = r[cidx] + cn[cidx];
        if (v < best || (v == best && cidx < bi)) { best = v; bi = cidx; }
    }
#pragma unroll
    for (int o = 16; o; o >>= 1) {
        float ov = __shfl_xor_sync(0xffffffffu, best, o);
        int   oi = __shfl_xor_sync(0xffffffffu, bi, o);
        if (ov < best || (ov == best && oi < bi)) { best = ov; bi = oi; }
    }
    if (lane == 0) idx[row] = bi;
}

__global__ void gather_kernel(const float* __restrict__ cb, const int* __restrict__ idx,
                              float* __restrict__ q) {
    long gid = (long)blockIdx.x * blockDim.x + threadIdx.x;
    if (gid >= 32768L * 128) return;
    int n  = (int)(gid >> 7);
    int d4 = (int)(gid & 127);
    reinterpret_cast<float4*>(q)[(long)n * 128 + d4] =
        reinterpret_cast<const float4*>(cb)[(long)idx[n] * 128 + d4];
}

__global__ void idx_to_float(const int* __restrict__ idx, float* __restrict__ out, int n) {
    int i = blockIdx.x * blockDim.x + threadIdx.x;
    if (i < n) out[i] = (float)idx[i];
}

// ----------------------------------------------------------------------------
extern "C" void kernel_launch(void* const* d_in, const int* in_sizes, int n_in,
                              void* d_out, int out_size) {
    const float* mels   = (const float*)d_in[0];
    const float* enc_w1 = (const float*)d_in[1];
    const float* enc_b1 = (const float*)d_in[2];
    const float* enc_w2 = (const float*)d_in[3];
    const float* enc_b2 = (const float*)d_in[4];
    const float* cb     = (const float*)d_in[5];
    const float* dec_w1 = (const float*)d_in[6];
    const float* dec_b1 = (const float*)d_in[7];
    const float* dec_w2 = (const float*)d_in[8];
    const float* dec_b2 = (const float*)d_in[9];

    float *bufA, *bufB, *scores, *wT, *cn;
    int*   idxp;
    cudaGetSymbolAddress((void**)&bufA,   g_bufA);
    cudaGetSymbolAddress((void**)&bufB,   g_bufB);
    cudaGetSymbolAddress((void**)&scores, g_scores);
    cudaGetSymbolAddress((void**)&wT,     g_wT);
    cudaGetSymbolAddress((void**)&cn,     g_cnorm);
    cudaGetSymbolAddress((void**)&idxp,   g_idx);

    const int B = 16, T = 2048, IN = 80, H = 512, D = 512, K = 1024;
    const int BT = B * T;
    const int RECON = B * T * IN;

    // ---- encoder conv1: mels[B,T,80] -> bufA, relu ----
    transpose_w<<<256, 256>>>(enc_w1, wT, H, IN, 3, H);
    conv_mma<3, true, true><<<dim3(T / 128, H / 128, B), 256>>>(
        mels, wT, enc_b1, bufA, T, IN, H, H, 1.f);

    // ---- encoder conv2: bufA -> bufB (z) ----
    transpose_w<<<256, 256>>>(enc_w2, wT, D, H, 3, D);
    conv_mma<3, false, true><<<dim3(T / 128, D / 128, B), 256>>>(
        bufA, wT, enc_b2, bufB, T, H, D, D, 1.f);

    // ---- VQ: scores[n,k] = -2 z_n . c_k ; argmin adds ||c_k||^2 ----
    cnorm_kernel<<<1024 / 8, 256>>>(cb, cn);
    transpose_w<<<256, 256>>>(cb, wT, K, D, 1, K);
    conv_mma<1, false, false><<<dim3(BT / 128, K / 128, 1), 256>>>(
        bufB, wT, nullptr, scores, BT, D, K, K, -2.f);
    argmin_kernel<<<BT / 8, 256>>>(scores, cn, idxp);
    gather_kernel<<<(BT * 128 + 255) / 256, 256>>>(cb, idxp, bufA);

    // ---- decoder conv1: bufA -> bufB, relu ----
    transpose_w<<<256, 256>>>(dec_w1, wT, H, D, 3, H);
    conv_mma<3, true, true><<<dim3(T / 128, H / 128, B), 256>>>(
        bufA, wT, dec_b1, bufB, T, D, H, H, 1.f);

    // ---- decoder conv2: bufB -> recon [B,T,80] (into d_out) ----
    transpose_w<<<256, 256>>>(dec_w2, wT, IN, H, 3, 128);
    float* recon = (float*)d_out;
    conv_mma<3, false, true><<<dim3(T / 128, 1, B), 256>>>(
        bufB, wT, dec_b2, recon, T, H, IN, 128, 1.f);

    if (out_size >= RECON + BT) {
        idx_to_float<<<(BT + 255) / 256, 256>>>(idxp, recon + RECON, BT);
    }
}